// round 17
// baseline (speedup 1.0000x reference)
#include <cuda_runtime.h>

// ---------------------------------------------------------------------------
// IMEX-ETD: CG-solve (I - DT*D*Lap_neumann) x = u, then pointwise ETD update.
// Round 17: TEMPORAL BLOCKING. Per-block halo tiles compute the full Krylov
// chain r0 -> s0 -> t in shared memory; r0/s0/t are NEVER materialized in HBM.
//   k_mom (halo 3): u,D in -> all 9 moments out (m03/m13/m23 via Lt in-tile:
//                   m_i3 = m_i2 - DT*(v_i, D.Lt), L symmetric-exact)
//   k_coef: 1-block moment assembly + 3-step CG trajectory (double)
//   k_etd (halo 2): recompute r0,s0 in smem, t in regs;
//                   out = ETD(u + c0 r0 + c1 s0 + c2 t)
// Total DRAM ~210MB (was ~570MB). Deterministic fixed-order reductions.
// ---------------------------------------------------------------------------

#define DT_C   0.1f
#define CG_TAU 0.015

#define IH     32          // tile interior height
#define IW     64          // tile interior width
#define NBLK   4096        // (1024/IH)*(1024/IW)*8 planes
#define PTHR   256

// k_mom tile (halo 3): regions R 38x70, S 36x68, T 34x66, M 32x64
#define MRH    38
#define MRW    70
#define MP     71          // pitch (odd)

// k_etd tile (halo 2): regions R' 36x68, S' 34x66, Out 32x64
#define ERH    36
#define ERW    68
#define EP     69

__device__ double g_pm[9][NBLK];
__device__ float  g_c[4];

// ---------------------------------------------------------------------------

__device__ __forceinline__ int clamp1023(int v) {
    return min(max(v, 0), 1023);
}

// float accumulator in, fixed-order double tree out (thread 0 valid)
__device__ __forceinline__ double block_reduce_f2d(float vf) {
    __shared__ double sh[PTHR / 32];
    double v = (double)vf;
    int lane = threadIdx.x & 31;
    int w    = threadIdx.x >> 5;
#pragma unroll
    for (int o = 16; o; o >>= 1) v += __shfl_down_sync(0xffffffffu, v, o);
    if (lane == 0) sh[w] = v;
    __syncthreads();
    if (w == 0) {
        v = (lane < PTHR / 32) ? sh[lane] : 0.0;
#pragma unroll
        for (int o = 16; o; o >>= 1) v += __shfl_down_sync(0xffffffffu, v, o);
    }
    return v;
}

// ---------------------------------------------------------------------------
// k_mom: one tile computes r0, s0, t in smem and all 9 moment partials.

__global__ void __launch_bounds__(PTHR) k_mom(const float* __restrict__ u,
                                              const float* __restrict__ Dg)
{
    __shared__ float sd[MRH * MP];            // D      (tile coords, off 0)
    __shared__ float sr[MRH * MP];            // r0     (off 0)
    __shared__ float ss[(MRH - 2) * MP];      // s0     (off 1)
    __shared__ float st[(MRH - 4) * MP];      // t      (off 2)

    const int b     = blockIdx.x;
    const int plane = b >> 9;                 // 512 tiles per plane
    const int tb    = b & 511;
    const int ty    = tb >> 4;                // 32 tile-rows
    const int tx    = tb & 15;                // 16 tile-cols
    const int gy0   = ty * IH;
    const int gx0   = tx * IW;
    const int base  = plane << 20;

    // ---- stage R: load D, compute r0 = DT*D*lap(u) (clamped global coords,
    //      halo cells get the value at the clamped position: finite) ----
    for (int idx = threadIdx.x; idx < MRH * MRW; idx += PTHR) {
        int ly = idx / MRW, lx = idx - ly * MRW;
        int gy = gy0 + ly - 3, gx = gx0 + lx - 3;
        int cy = clamp1023(gy),     cx = clamp1023(gx);
        int yT = clamp1023(gy - 1), yB = clamp1023(gy + 1);
        int xL = clamp1023(gx - 1), xR = clamp1023(gx + 1);
        float uc = __ldg(u + base + cy * 1024 + cx);
        float uT = __ldg(u + base + yT * 1024 + cx);
        float uB = __ldg(u + base + yB * 1024 + cx);
        float uL = __ldg(u + base + cy * 1024 + xL);
        float uR = __ldg(u + base + cy * 1024 + xR);
        float d  = __ldg(Dg + base + cy * 1024 + cx);
        float lap = (uL + uR) + (uT + uB) - 4.0f * uc;
        sd[ly * MP + lx] = d;
        sr[ly * MP + lx] = DT_C * d * lap;
    }
    __syncthreads();

    // ---- stage S: s0 = r0 - DT*D*lap(r0), region [1,37)x[1,69) ----
    for (int idx = threadIdx.x; idx < (MRH - 2) * (MRW - 2); idx += PTHR) {
        int ly = idx / (MRW - 2) + 1, lx = idx % (MRW - 2) + 1;
        int gy = gy0 + ly - 3, gx = gx0 + lx - 3;
        float rc = sr[ly * MP + lx];
        float rT = (gy > 0)    ? sr[(ly - 1) * MP + lx] : rc;
        float rB = (gy < 1023) ? sr[(ly + 1) * MP + lx] : rc;
        float rL = (gx > 0)    ? sr[ly * MP + lx - 1]   : rc;
        float rR = (gx < 1023) ? sr[ly * MP + lx + 1]   : rc;
        float lap = (rL + rR) + (rT + rB) - 4.0f * rc;
        ss[(ly - 1) * MP + (lx - 1)] = fmaf(-DT_C * sd[ly * MP + lx], lap, rc);
    }
    __syncthreads();

    // ---- stage T: t = s0 - DT*D*lap(s0), region [2,36)x[2,68) ----
    for (int idx = threadIdx.x; idx < (MRH - 4) * (MRW - 4); idx += PTHR) {
        int ly = idx / (MRW - 4) + 2, lx = idx % (MRW - 4) + 2;
        int gy = gy0 + ly - 3, gx = gx0 + lx - 3;
        float sc = ss[(ly - 1) * MP + (lx - 1)];
        float sT = (gy > 0)    ? ss[(ly - 2) * MP + (lx - 1)] : sc;
        float sB = (gy < 1023) ? ss[ly * MP + (lx - 1)]       : sc;
        float sL = (gx > 0)    ? ss[(ly - 1) * MP + (lx - 2)] : sc;
        float sR = (gx < 1023) ? ss[(ly - 1) * MP + lx]       : sc;
        float lap = (sL + sR) + (sT + sB) - 4.0f * sc;
        st[(ly - 2) * MP + (lx - 2)] = fmaf(-DT_C * sd[ly * MP + lx], lap, sc);
    }
    __syncthreads();

    // ---- stage M: interior dots; Lt available in-tile ----
    float a00 = 0.0f, a01 = 0.0f, a11 = 0.0f, a02 = 0.0f, a12 = 0.0f;
    float a22 = 0.0f, a03 = 0.0f, a13 = 0.0f, a23 = 0.0f;
    for (int idx = threadIdx.x; idx < IH * IW; idx += PTHR) {
        int ly = (idx >> 6) + 3, lx = (idx & 63) + 3;
        int gy = gy0 + ly - 3, gx = gx0 + lx - 3;
        float r  = sr[ly * MP + lx];
        float s  = ss[(ly - 1) * MP + (lx - 1)];
        float tc = st[(ly - 2) * MP + (lx - 2)];
        float d  = sd[ly * MP + lx];
        float tT = (gy > 0)    ? st[(ly - 3) * MP + (lx - 2)] : tc;
        float tB = (gy < 1023) ? st[(ly - 1) * MP + (lx - 2)] : tc;
        float tL = (gx > 0)    ? st[(ly - 2) * MP + (lx - 3)] : tc;
        float tR = (gx < 1023) ? st[(ly - 2) * MP + (lx - 1)] : tc;
        float Lt = (tL + tR) + (tT + tB) - 4.0f * tc;
        float g  = d * Lt;
        a00 = fmaf(r, r,  a00);
        a01 = fmaf(r, s,  a01);
        a11 = fmaf(s, s,  a11);
        a02 = fmaf(r, tc, a02);
        a12 = fmaf(s, tc, a12);
        a22 = fmaf(tc, tc, a22);
        a03 = fmaf(r, g,  a03);
        a13 = fmaf(s, g,  a13);
        a23 = fmaf(tc, g, a23);
    }
    float acc[9] = {a00, a01, a11, a12, a22, a02, a03, a13, a23};
#pragma unroll
    for (int q = 0; q < 9; q++) {
        __syncthreads();
        double v = block_reduce_f2d(acc[q]);
        if (threadIdx.x == 0) g_pm[q][b] = v;
    }
}

// ---------------------------------------------------------------------------
// k_coef (1 block): assemble moments, run 3-step CG trajectory in double.
// partial order: 0:m00 1:m01 2:m11 3:m12 4:m22 5:m02 6:a03 7:a13 8:a23

__global__ void __launch_bounds__(1024) k_coef()
{
    __shared__ double mom[9];
    int lane = threadIdx.x & 31;
    int w    = threadIdx.x >> 5;
    if (w < 9) {
        double s = 0.0;
        for (int j = lane; j < NBLK; j += 32) s += g_pm[w][j];
#pragma unroll
        for (int o = 16; o; o >>= 1) s += __shfl_down_sync(0xffffffffu, s, o);
        if (lane == 0) mom[w] = s;
    }
    __syncthreads();
    if (threadIdx.x == 0) {
        const double DTd = (double)DT_C;
        double m00 = mom[0], m01 = mom[1], m11 = mom[2];
        double m12 = mom[3], m22 = mom[4], m02 = mom[5];
        double m03 = m02 - DTd * mom[6];   // (r0, A t) = m02 - DT*(r0, D.Lt)
        double m13 = m12 - DTd * mom[7];
        double m23 = m22 - DTd * mom[8];

        double M[4][4];
        M[0][0] = m00; M[0][1] = m01; M[0][2] = m02; M[0][3] = m03;
        M[1][0] = m01; M[1][1] = m11; M[1][2] = m12; M[1][3] = m13;
        M[2][0] = m02; M[2][1] = m12; M[2][2] = m22; M[2][3] = m23;
        M[3][0] = m03; M[3][1] = m13; M[3][2] = m23; M[3][3] = 0.0;

        double rv[4] = {1.0, 0.0, 0.0, 0.0};
        double pv[4] = {1.0, 0.0, 0.0, 0.0};
        double xv[4] = {0.0, 0.0, 0.0, 0.0};
        double rs = m00;

        for (int step = 0; step < 3; step++) {
            double Apv[4] = {0.0, pv[0], pv[1], pv[2]};
            double pAp = 0.0;
            for (int i = 0; i < 4; i++)
                for (int jq = 0; jq < 4; jq++)
                    pAp += pv[i] * M[i][jq] * Apv[jq];
            float af = (float)(rs / (pAp + 1e-300));
            double ad = (double)af;
            for (int i = 0; i < 4; i++) {
                xv[i] += ad * pv[i];
                rv[i] -= ad * Apv[i];
            }
            if (step == 2) break;
            double rs_new = 0.0;
            for (int i = 0; i < 4; i++)
                for (int jq = 0; jq < 4; jq++)
                    rs_new += rv[i] * M[i][jq] * rv[jq];
            if (rs_new < 0.0) rs_new = 0.0;
            if (sqrt(rs_new) < CG_TAU) break;
            float bf = (float)(rs_new / (rs + 1e-300));
            double bd = (double)bf;
            for (int i = 0; i < 4; i++) pv[i] = rv[i] + bd * pv[i];
            rs = rs_new;
        }
        g_c[0] = (float)xv[0];
        g_c[1] = (float)xv[1];
        g_c[2] = (float)xv[2];
        g_c[3] = 0.0f;
    }
}

// ---------------------------------------------------------------------------
// k_etd: recompute r0, s0 (smem, halo 2), t (regs); ETD; write out.

__global__ void __launch_bounds__(PTHR) k_etd(const float* __restrict__ u,
                                              const float* __restrict__ Dg,
                                              const float* __restrict__ kp,
                                              const float* __restrict__ aCp,
                                              const float* __restrict__ Ctp,
                                              float* __restrict__ out)
{
    __shared__ float sd[ERH * EP];
    __shared__ float sr[ERH * EP];
    __shared__ float ss[(ERH - 2) * EP];

    const int b     = blockIdx.x;
    const int plane = b >> 9;
    const int tb    = b & 511;
    const int ty    = tb >> 4;
    const int tx    = tb & 15;
    const int gy0   = ty * IH;
    const int gx0   = tx * IW;
    const int base  = plane << 20;

    const float c0 = g_c[0], c1 = g_c[1], c2 = g_c[2];
    const float kk = __ldg(&kp[0]);
    const float a  = kk - __ldg(&aCp[0]) * __ldg(&Ctp[0]);
    const float bc = kk;                         // k / K_CAP, K_CAP = 1
    const float adc = fminf(fmaxf(a * DT_C, -60.0f), 60.0f);
    const float e   = expf(adc);
    const float em1 = e - 1.0f;

    // ---- stage R': load D, r0 = DT*D*lap(u), region 36x68, halo 2 ----
    for (int idx = threadIdx.x; idx < ERH * ERW; idx += PTHR) {
        int ly = idx / ERW, lx = idx - ly * ERW;
        int gy = gy0 + ly - 2, gx = gx0 + lx - 2;
        int cy = clamp1023(gy),     cx = clamp1023(gx);
        int yT = clamp1023(gy - 1), yB = clamp1023(gy + 1);
        int xL = clamp1023(gx - 1), xR = clamp1023(gx + 1);
        float uc = __ldg(u + base + cy * 1024 + cx);
        float uT = __ldg(u + base + yT * 1024 + cx);
        float uB = __ldg(u + base + yB * 1024 + cx);
        float uL = __ldg(u + base + cy * 1024 + xL);
        float uR = __ldg(u + base + cy * 1024 + xR);
        float d  = __ldg(Dg + base + cy * 1024 + cx);
        float lap = (uL + uR) + (uT + uB) - 4.0f * uc;
        sd[ly * EP + lx] = d;
        sr[ly * EP + lx] = DT_C * d * lap;
    }
    __syncthreads();

    // ---- stage S': s0 = A r0, region [1,35)x[1,67) ----
    for (int idx = threadIdx.x; idx < (ERH - 2) * (ERW - 2); idx += PTHR) {
        int ly = idx / (ERW - 2) + 1, lx = idx % (ERW - 2) + 1;
        int gy = gy0 + ly - 2, gx = gx0 + lx - 2;
        float rc = sr[ly * EP + lx];
        float rT = (gy > 0)    ? sr[(ly - 1) * EP + lx] : rc;
        float rB = (gy < 1023) ? sr[(ly + 1) * EP + lx] : rc;
        float rL = (gx > 0)    ? sr[ly * EP + lx - 1]   : rc;
        float rR = (gx < 1023) ? sr[ly * EP + lx + 1]   : rc;
        float lap = (rL + rR) + (rT + rB) - 4.0f * rc;
        ss[(ly - 1) * EP + (lx - 1)] = fmaf(-DT_C * sd[ly * EP + lx], lap, rc);
    }
    __syncthreads();

    // ---- stage Out: t in regs; ETD; write ----
    for (int idx = threadIdx.x; idx < IH * IW; idx += PTHR) {
        int ly = (idx >> 6) + 2, lx = (idx & 63) + 2;
        int gy = gy0 + ly - 2, gx = gx0 + lx - 2;
        float sc = ss[(ly - 1) * EP + (lx - 1)];
        float sT = (gy > 0)    ? ss[(ly - 2) * EP + (lx - 1)] : sc;
        float sB = (gy < 1023) ? ss[ly * EP + (lx - 1)]       : sc;
        float sL = (gx > 0)    ? ss[(ly - 1) * EP + (lx - 2)] : sc;
        float sR = (gx < 1023) ? ss[(ly - 1) * EP + lx]       : sc;
        float lap = (sL + sR) + (sT + sB) - 4.0f * sc;
        float tv = fmaf(-DT_C * sd[ly * EP + lx], lap, sc);

        float rv = sr[ly * EP + lx];
        float uv = __ldg(u + base + gy * 1024 + gx);
        float ut = fmaf(c2, tv, fmaf(c1, sc, fmaf(c0, rv, uv)));

        float num = a * ut * e;
        float den = fmaf(bc * ut, em1, a);
        float un  = (fabsf(den) > 1e-12f) ? (num / den) : ut;
        un = fminf(fmaxf(un, 0.0f), 1.0f);
        out[base + gy * 1024 + gx] = un;
    }
}

// ---------------------------------------------------------------------------

extern "C" void kernel_launch(void* const* d_in, const int* in_sizes, int n_in,
                              void* d_out, int out_size)
{
    const float* u   = (const float*)d_in[0];
    const float* D   = (const float*)d_in[1];
    const float* k   = (const float*)d_in[2];
    const float* aC  = (const float*)d_in[3];
    const float* C_t = (const float*)d_in[4];
    float* out = (float*)d_out;

    k_mom <<<NBLK, PTHR>>>(u, D);
    k_coef<<<1, 1024>>>();
    k_etd <<<NBLK, PTHR>>>(u, D, k, aC, C_t, out);
}